// round 8
// baseline (speedup 1.0000x reference)
#include <cuda_runtime.h>
#include <cuda_bf16.h>

// Problem constants
#define NN 2048
#define DD 128
#define HH 64

typedef unsigned long long u64;
typedef union { u64 v; float2 f; } uf2;

// ---------- scratch (device globals; no allocation allowed) ----------
__device__ float g_pi [NN * HH];   // agent @ W1a
__device__ float g_pjt[NN * HH];   // agent @ W1b + task @ W1c + b1

// ---------- packed f32x2 helpers (sm_100+) ----------
__device__ __forceinline__ u64 f2add(u64 a, u64 b) {
    u64 r; asm("add.rn.f32x2 %0, %1, %2;" : "=l"(r) : "l"(a), "l"(b)); return r;
}
__device__ __forceinline__ u64 f2fma(u64 a, u64 b, u64 c) {
    u64 r; asm("fma.rn.f32x2 %0, %1, %2, %3;" : "=l"(r) : "l"(a), "l"(b), "l"(c)); return r;
}

// ---------- k1: pi / pjt projections, task projection fused ----------
__global__ __launch_bounds__(256) void k1_proj(const float* __restrict__ z,
                                               const float* __restrict__ W1,
                                               const float* __restrict__ b1) {
    __shared__ float zs[8][DD];
    __shared__ float zt[DD];
    __shared__ float ptp[4][HH];   // partial task-projection sums
    int tid = threadIdx.x;
    int hp  = tid & 31;            // h pair index -> h = 2*hp
    int r   = tid >> 5;            // 0..7, one row each
    int row_base = blockIdx.x * 8;

    // stage 8 agent rows: exactly 1 float4 per thread
    {
        int rr = tid >> 5, c = (tid & 31) << 2;
        *(float4*)&zs[rr][c] = *(const float4*)&z[(row_base + rr) * DD + c];
    }
    // stage task row (last row of z)
    if (tid < DD / 4)
        *(float4*)&zt[tid << 2] = *(const float4*)&z[NN * DD + (tid << 2)];
    __syncthreads();

    // pt partials: 256 threads = 64 h * 4 k-chunks of 32
    {
        int h = tid & 63, chunk = tid >> 6;
        const float* w = W1 + (2 * DD + chunk * 32) * HH + h;
        float s = 0.f;
#pragma unroll 8
        for (int k = 0; k < 32; k++) s = fmaf(zt[chunk * 32 + k], w[k * HH], s);
        ptp[chunk][h] = s;
    }

    // per-thread row projections
    float2 pa = {0.f, 0.f}, pb = {0.f, 0.f};
    const float* wA = W1 + 2 * hp;
    const float* wB = W1 + DD * HH + 2 * hp;
#pragma unroll 8
    for (int k = 0; k < DD; k++) {
        float2 wa = *(const float2*)(wA + k * HH);
        float2 wb = *(const float2*)(wB + k * HH);
        float zv = zs[r][k];
        pa.x = fmaf(zv, wa.x, pa.x);  pa.y = fmaf(zv, wa.y, pa.y);
        pb.x = fmaf(zv, wb.x, pb.x);  pb.y = fmaf(zv, wb.y, pb.y);
    }
    __syncthreads();   // ptp ready

    float ptx = b1[2 * hp]     + ptp[0][2 * hp]     + ptp[1][2 * hp]
              + ptp[2][2 * hp] + ptp[3][2 * hp];
    float pty = b1[2 * hp + 1] + ptp[0][2 * hp + 1] + ptp[1][2 * hp + 1]
              + ptp[2][2 * hp + 1] + ptp[3][2 * hp + 1];

    int gr = row_base + r;
    *(float2*)&g_pi[gr * HH + 2 * hp] = pa;
    pb.x += ptx;  pb.y += pty;
    *(float2*)&g_pjt[gr * HH + 2 * hp] = pb;
}

// ---------- main: out[i,j] = sigmoid(w_ij + gumbel(eps)) ----------
// CTA tile: 64 x 64. 256 threads = 16 tx * 16 ty, thread tile 4x4.
// Slim smem (34 KB) + __launch_bounds__(256,5): 5 CTAs/SM = 10 warps/SMSP.
// eps read directly in epilogue (16 LDG/thread, MLP-overlapped).
#define TI 64
#define TJ 64
#define PSTRIDE 66               // pad: conflict-free LDS.64 across tx

__global__ __launch_bounds__(256, 5) void main_kernel(const float* __restrict__ W2,
                                                      const float* __restrict__ b2,
                                                      const float* __restrict__ eps,
                                                      float* __restrict__ out) {
    extern __shared__ float smem[];
    float* pi_s  = smem;                        // 64 * 66
    float* pjt_s = smem + TI * PSTRIDE;         // 64 * 66
    float* c_s   = pjt_s + TJ * PSTRIDE;        // 64 (W2)

    int tid = threadIdx.x;
    int tx = tid & 15, ty = tid >> 4;
    int it0 = blockIdx.y * TI;
    int jt0 = blockIdx.x * TJ;

    // stage pi tile (float2 into padded stride)
    for (int idx = tid; idx < TI * HH / 2; idx += 256) {
        int r = idx >> 5;
        int c = (idx & 31) << 1;
        *(float2*)&pi_s[r * PSTRIDE + c] = *(const float2*)&g_pi[(it0 + r) * HH + c];
    }
    // stage pjt tile
    for (int idx = tid; idx < TJ * HH / 2; idx += 256) {
        int r = idx >> 5;
        int c = (idx & 31) << 1;
        *(float2*)&pjt_s[r * PSTRIDE + c] = *(const float2*)&g_pjt[(jt0 + r) * HH + c];
    }
    if (tid < HH) c_s[tid] = W2[tid];
    __syncthreads();

    u64 acc[4][4];
#pragma unroll
    for (int r = 0; r < 4; r++)
#pragma unroll
        for (int q = 0; q < 4; q++) acc[r][q] = 0ull;

#pragma unroll 8
    for (int hp = 0; hp < HH / 2; hp++) {
        u64 c2 = *(const u64*)&c_s[2 * hp];
        u64 a[4], b[4];
#pragma unroll
        for (int r = 0; r < 4; r++)
            a[r] = *(const u64*)&pi_s[(ty + 16 * r) * PSTRIDE + 2 * hp];
#pragma unroll
        for (int q = 0; q < 4; q++)
            b[q] = *(const u64*)&pjt_s[(tx + 16 * q) * PSTRIDE + 2 * hp];
#pragma unroll
        for (int r = 0; r < 4; r++) {
#pragma unroll
            for (int q = 0; q < 4; q++) {
                uf2 t;
                t.v = f2add(a[r], b[q]);               // FADD2 (fma pipe)
                t.f.x = fmaxf(t.f.x, 0.f);             // FMNMX (alu pipe)
                t.f.y = fmaxf(t.f.y, 0.f);             // FMNMX (alu pipe)
                acc[r][q] = f2fma(t.v, c2, acc[r][q]); // FFMA2 (fma pipe)
            }
        }
    }

    float b2v = b2[0];
#pragma unroll
    for (int r = 0; r < 4; r++) {
#pragma unroll
        for (int q = 0; q < 4; q++) {
            uf2 s; s.v = acc[r][q];
            float w = s.f.x + s.f.y + b2v;
            int i = it0 + ty + 16 * r;
            int j = jt0 + tx + 16 * q;
            float e = eps[(u64)i * NN + j] + 1e-8f;
            // sigmoid(w + log e - log(1-e)) = e / (e + exp(-w)*(1-e))
            float qe = __expf(-w);
            float d  = fmaf(-qe, e, qe) + e;
            out[(u64)i * NN + j] = __fdividef(e, d);
        }
    }
}

// ---------- launch ----------
extern "C" void kernel_launch(void* const* d_in, const int* in_sizes, int n_in,
                              void* d_out, int out_size) {
    const float* z   = (const float*)d_in[0];   // (2049, 128)
    const float* W1  = (const float*)d_in[1];   // (384, 64)
    const float* b1  = (const float*)d_in[2];   // (64,)
    const float* W2  = (const float*)d_in[3];   // (64, 1)
    const float* b2  = (const float*)d_in[4];   // (1,)
    const float* eps = (const float*)d_in[5];   // (2048, 2048)
    float* out = (float*)d_out;                 // (2048, 2048)

    k1_proj<<<NN / 8, 256>>>(z, W1, b1);

    size_t smem_bytes = ((TI + TJ) * PSTRIDE + HH) * sizeof(float); // 34048 B
    cudaFuncSetAttribute(main_kernel, cudaFuncAttributeMaxDynamicSharedMemorySize,
                         (int)smem_bytes);
    dim3 grid(NN / TJ, NN / TI);   // 32 x 32 = 1024 CTAs
    main_kernel<<<grid, 256, smem_bytes>>>(W2, b2, eps, out);
}

// round 11
// speedup vs baseline: 1.2537x; 1.2537x over previous
#include <cuda_runtime.h>
#include <cuda_bf16.h>

// Problem constants
#define NN 2048
#define DD 128
#define HH 64

typedef unsigned long long u64;
typedef union { u64 v; float2 f; } uf2;

// ---------- scratch (device globals; no allocation allowed) ----------
__device__ float g_pi [NN * HH];   // agent @ W1a
__device__ float g_pjt[NN * HH];   // agent @ W1b + task @ W1c + b1

// ---------- packed f32x2 helpers (sm_100+) ----------
__device__ __forceinline__ u64 f2add(u64 a, u64 b) {
    u64 r; asm("add.rn.f32x2 %0, %1, %2;" : "=l"(r) : "l"(a), "l"(b)); return r;
}
__device__ __forceinline__ u64 f2fma(u64 a, u64 b, u64 c) {
    u64 r; asm("fma.rn.f32x2 %0, %1, %2, %3;" : "=l"(r) : "l"(a), "l"(b), "l"(c)); return r;
}

// ---------- k1: pi / pjt projections, task projection fused ----------
// 512 blocks x 4 rows. 2-way k-split per row: each thread does 64 k-iters
// (half chain), partials combined via smem.
__global__ __launch_bounds__(256) void k1_proj(const float* __restrict__ z,
                                               const float* __restrict__ W1,
                                               const float* __restrict__ b1) {
    __shared__ float zs[4][DD];
    __shared__ float zt[DD];
    __shared__ float ptp[4][HH];          // task-projection partials
    __shared__ float psum[4][HH * 2];     // k-half-1 partials: [row][2h: pa,pb interleaved]
    int tid = threadIdx.x;
    int hp  = tid & 31;                   // h pair -> h = 2*hp
    int r   = (tid >> 5) & 3;             // row 0..3
    int kh  = tid >> 7;                   // k-half 0/1
    int row_base = blockIdx.x * 4;

    // stage 4 agent rows (128 float4 by first 128 threads)
    if (tid < 128) {
        int rr = tid >> 5, c = (tid & 31) << 2;
        *(float4*)&zs[rr][c] = *(const float4*)&z[(row_base + rr) * DD + c];
    }
    // stage task row (last row of z)
    if (tid >= 128 && tid < 160)
        *(float4*)&zt[(tid - 128) << 2] = *(const float4*)&z[NN * DD + ((tid - 128) << 2)];
    __syncthreads();

    // pt partials: 256 threads = 64 h * 4 k-chunks of 32
    {
        int h = tid & 63, chunk = tid >> 6;
        const float* w = W1 + (2 * DD + chunk * 32) * HH + h;
        float s = 0.f;
#pragma unroll 8
        for (int k = 0; k < 32; k++) s = fmaf(zt[chunk * 32 + k], w[k * HH], s);
        ptp[chunk][h] = s;
    }

    // per-thread half-row projections: k in [kh*64, kh*64+64)
    float2 pa = {0.f, 0.f}, pb = {0.f, 0.f};
    {
        const float* wA = W1 + (kh * 64) * HH + 2 * hp;
        const float* wB = W1 + (DD + kh * 64) * HH + 2 * hp;
        const float* zr = &zs[r][kh * 64];
#pragma unroll 8
        for (int k = 0; k < 64; k++) {
            float2 wa = *(const float2*)(wA + k * HH);
            float2 wb = *(const float2*)(wB + k * HH);
            float zv = zr[k];
            pa.x = fmaf(zv, wa.x, pa.x);  pa.y = fmaf(zv, wa.y, pa.y);
            pb.x = fmaf(zv, wb.x, pb.x);  pb.y = fmaf(zv, wb.y, pb.y);
        }
    }
    // k-half 1 publishes partials
    if (kh == 1) {
        *(float2*)&psum[r][4 * hp]     = pa;
        *(float2*)&psum[r][4 * hp + 2] = pb;
    }
    __syncthreads();

    if (kh == 0) {
        float2 pa1 = *(const float2*)&psum[r][4 * hp];
        float2 pb1 = *(const float2*)&psum[r][4 * hp + 2];
        pa.x += pa1.x;  pa.y += pa1.y;
        pb.x += pb1.x;  pb.y += pb1.y;

        float ptx = b1[2 * hp]     + ptp[0][2 * hp]     + ptp[1][2 * hp]
                  + ptp[2][2 * hp] + ptp[3][2 * hp];
        float pty = b1[2 * hp + 1] + ptp[0][2 * hp + 1] + ptp[1][2 * hp + 1]
                  + ptp[2][2 * hp + 1] + ptp[3][2 * hp + 1];

        int gr = row_base + r;
        *(float2*)&g_pi[gr * HH + 2 * hp] = pa;
        pb.x += ptx;  pb.y += pty;
        *(float2*)&g_pjt[gr * HH + 2 * hp] = pb;
    }
}

// ---------- main: out[i,j] = sigmoid(w_ij + gumbel(eps)) ----------
// CTA tile: 64 x 64. 256 threads = 16 tx * 16 ty, thread tile 4x4.
// PDL: eps cp.async prefetch issued pre-sync (overlaps k1), then
// cudaGridDependencySynchronize() before consuming g_pi/g_pjt.
#define TI 64
#define TJ 64
#define PSTRIDE 66               // pad: conflict-free LDS.64 across tx

__global__ __launch_bounds__(256, 4) void main_kernel(const float* __restrict__ W2,
                                                      const float* __restrict__ b2,
                                                      const float* __restrict__ eps,
                                                      float* __restrict__ out) {
    extern __shared__ float smem[];
    float* pi_s  = smem;                        // 64 * 66
    float* pjt_s = smem + TI * PSTRIDE;         // 64 * 66
    float* c_s   = pjt_s + TJ * PSTRIDE;        // 64 (W2)
    float* eps_s = c_s + HH;                    // 64 * 64

    int tid = threadIdx.x;
    int tx = tid & 15, ty = tid >> 4;
    int it0 = blockIdx.y * TI;
    int jt0 = blockIdx.x * TJ;

    // ---- pre-sync section: independent of k1 output ----
    // eps tile prefetch (4 x cp.async.128 per thread)
#pragma unroll
    for (int it = 0; it < 4; it++) {
        int idx = tid + 256 * it;
        int row = idx >> 4;
        int col = (idx & 15) << 2;
        unsigned dst = (unsigned)__cvta_generic_to_shared(&eps_s[row * TJ + col]);
        const float* src = eps + (u64)(it0 + row) * NN + jt0 + col;
        asm volatile("cp.async.ca.shared.global [%0], [%1], 16;" :: "r"(dst), "l"(src));
    }
    asm volatile("cp.async.commit_group;");
    if (tid < HH) c_s[tid] = W2[tid];

    // ---- wait for k1 (PDL) ----
    cudaGridDependencySynchronize();

    // stage pi tile (float2 into padded stride)
    for (int idx = tid; idx < TI * HH / 2; idx += 256) {
        int r = idx >> 5;
        int c = (idx & 31) << 1;
        *(float2*)&pi_s[r * PSTRIDE + c] = *(const float2*)&g_pi[(it0 + r) * HH + c];
    }
    // stage pjt tile
    for (int idx = tid; idx < TJ * HH / 2; idx += 256) {
        int r = idx >> 5;
        int c = (idx & 31) << 1;
        *(float2*)&pjt_s[r * PSTRIDE + c] = *(const float2*)&g_pjt[(jt0 + r) * HH + c];
    }
    __syncthreads();

    u64 acc[4][4];
#pragma unroll
    for (int r = 0; r < 4; r++)
#pragma unroll
        for (int q = 0; q < 4; q++) acc[r][q] = 0ull;

#pragma unroll 4
    for (int hp = 0; hp < HH / 2; hp++) {
        u64 c2 = *(const u64*)&c_s[2 * hp];
        u64 a[4], b[4];
#pragma unroll
        for (int r = 0; r < 4; r++)
            a[r] = *(const u64*)&pi_s[(ty + 16 * r) * PSTRIDE + 2 * hp];
#pragma unroll
        for (int q = 0; q < 4; q++)
            b[q] = *(const u64*)&pjt_s[(tx + 16 * q) * PSTRIDE + 2 * hp];
#pragma unroll
        for (int r = 0; r < 4; r++) {
#pragma unroll
            for (int q = 0; q < 4; q++) {
                uf2 t;
                t.v = f2add(a[r], b[q]);               // FADD2 (fma pipe)
                t.f.x = fmaxf(t.f.x, 0.f);             // FMNMX (alu pipe)
                t.f.y = fmaxf(t.f.y, 0.f);             // FMNMX (alu pipe)
                acc[r][q] = f2fma(t.v, c2, acc[r][q]); // FFMA2 (fma pipe)
            }
        }
    }

    // eps tile must be fully landed before reading
    asm volatile("cp.async.wait_group 0;");
    __syncthreads();

    float b2v = b2[0];
#pragma unroll
    for (int r = 0; r < 4; r++) {
#pragma unroll
        for (int q = 0; q < 4; q++) {
            uf2 s; s.v = acc[r][q];
            float w = s.f.x + s.f.y + b2v;
            int i = it0 + ty + 16 * r;
            int j = jt0 + tx + 16 * q;
            float e = eps_s[(ty + 16 * r) * TJ + (tx + 16 * q)] + 1e-8f;
            // sigmoid(w + log e - log(1-e)) = e / (e + exp(-w)*(1-e))
            float qe = __expf(-w);
            float d  = fmaf(-qe, e, qe) + e;
            out[(u64)i * NN + j] = __fdividef(e, d);
        }
    }
}

// ---------- launch ----------
extern "C" void kernel_launch(void* const* d_in, const int* in_sizes, int n_in,
                              void* d_out, int out_size) {
    const float* z   = (const float*)d_in[0];   // (2049, 128)
    const float* W1  = (const float*)d_in[1];   // (384, 64)
    const float* b1  = (const float*)d_in[2];   // (64,)
    const float* W2  = (const float*)d_in[3];   // (64, 1)
    const float* b2  = (const float*)d_in[4];   // (1,)
    const float* eps = (const float*)d_in[5];   // (2048, 2048)
    float* out = (float*)d_out;                 // (2048, 2048)

    k1_proj<<<NN / 4, 256>>>(z, W1, b1);

    size_t smem_bytes = ((TI + TJ) * PSTRIDE + HH + TI * TJ) * sizeof(float); // 50432 B
    cudaFuncSetAttribute(main_kernel, cudaFuncAttributeMaxDynamicSharedMemorySize,
                         (int)smem_bytes);

    // PDL launch: main may start while k1 runs; gridDependencySynchronize
    // inside main orders the g_pi/g_pjt consumption.
    cudaLaunchConfig_t cfg = {};
    cfg.gridDim  = dim3(NN / TJ, NN / TI, 1);   // 32 x 32 = 1024 CTAs
    cfg.blockDim = dim3(256, 1, 1);
    cfg.dynamicSmemBytes = smem_bytes;
    cfg.stream = 0;
    cudaLaunchAttribute attr[1];
    attr[0].id = cudaLaunchAttributeProgrammaticStreamSerialization;
    attr[0].val.programmaticStreamSerializationAllowed = 1;
    cfg.attrs = attr;
    cfg.numAttrs = 1;
    cudaLaunchKernelEx(&cfg, main_kernel, W2, b2, eps, out);
}